// round 15
// baseline (speedup 1.0000x reference)
#include <cuda_runtime.h>
#include <stdint.h>
#include <math.h>

#define NF 64
#define NPAIR 2016
#define RSTR 68                      // stage row stride (floats): even (STS.64) + 2-way-min banks
#define STGF (16 * RSTR)             // per-warp stage floats (one 16-row strip)

__device__ __forceinline__ void mma4(float* c,
                                     uint32_t a0, uint32_t a1, uint32_t a2, uint32_t a3,
                                     uint32_t b0, uint32_t b1) {
    asm volatile(
        "mma.sync.aligned.m16n8k16.row.col.f32.bf16.bf16.f32 "
        "{%0,%1,%2,%3}, {%4,%5,%6,%7}, {%8,%9}, {%0,%1,%2,%3};"
        : "+f"(c[0]), "+f"(c[1]), "+f"(c[2]), "+f"(c[3])
        : "r"(a0), "r"(a1), "r"(a2), "r"(a3), "r"(b0), "r"(b1));
}

// Strip R: rows [16R,16R+16). A fragments are reused B-tile registers.
// Accumulators stored UNGUARDED as aligned STS.64 into a row-major strip
// stage; packed copy-out gathers (i,j) via exact sqrt inversion.
template<int R>
__device__ __forceinline__ void strip(const uint32_t Bh[8][4],
                                      const uint32_t Bl[8][4],
                                      float* st, float* outp, int lane)
{
    constexpr int S0 = (16 * R * (127 - 16 * R)) / 2;   // 0, 888, 1520, 1896
    constexpr int SZ = 888 - 256 * R;                   // 888, 632, 376, 120

    const int r0l = lane >> 2;                // strip-local rows: r0l, r0l+8
    float* row0 = st + r0l * RSTR + 2 * (lane & 3);
    float* row1 = row0 + 8 * RSTR;

    #pragma unroll
    for (int t = 2 * R; t < 8; ++t) {
        float c[4] = {0.f, 0.f, 0.f, 0.f};
        // hi.hi
        mma4(c, Bh[2*R][0], Bh[2*R+1][0], Bh[2*R][1], Bh[2*R+1][1], Bh[t][0], Bh[t][1]);
        mma4(c, Bh[2*R][2], Bh[2*R+1][2], Bh[2*R][3], Bh[2*R+1][3], Bh[t][2], Bh[t][3]);
        // hi.lo
        mma4(c, Bh[2*R][0], Bh[2*R+1][0], Bh[2*R][1], Bh[2*R+1][1], Bl[t][0], Bl[t][1]);
        mma4(c, Bh[2*R][2], Bh[2*R+1][2], Bh[2*R][3], Bh[2*R+1][3], Bl[t][2], Bl[t][3]);
        // lo.hi
        mma4(c, Bl[2*R][0], Bl[2*R+1][0], Bl[2*R][1], Bl[2*R+1][1], Bh[t][0], Bh[t][1]);
        mma4(c, Bl[2*R][2], Bl[2*R+1][2], Bl[2*R][3], Bl[2*R+1][3], Bh[t][2], Bh[t][3]);

        // unguarded aligned 8-byte stores (garbage below diagonal never read)
        *(float2*)(row0 + 8 * t) = make_float2(c[0], c[1]);
        *(float2*)(row1 + 8 * t) = make_float2(c[2], c[3]);
    }
    __syncwarp();

    // packed copy-out: invert p -> (i,j), gather from row-major stage
    constexpr int QUADS = SZ / 4;            // 222, 158, 94, 30
    #pragma unroll
    for (int qb = 0; qb < (QUADS + 31) / 32; ++qb) {
        int q = lane + qb * 32;
        if (QUADS % 32 == 0 || q < QUADS) {
            int p = S0 + q * 4;
            int i = (int)((127.0f - sqrtf(16129.0f - 8.0f * (float)p)) * 0.5f);
            while (((i + 1) * (126 - i)) >> 1 <= p) ++i;   // fixups guard rounding
            while ((i * (127 - i)) >> 1 > p) --i;
            int j = i + 1 + (p - ((i * (127 - i)) >> 1));

            const float* row = st + (i - 16 * R) * RSTR;
            float4 v;
            v.x = row[j]; if (++j == NF) { ++i; row += RSTR; j = i + 1; }
            v.y = row[j]; if (++j == NF) { ++i; row += RSTR; j = i + 1; }
            v.z = row[j]; if (++j == NF) { ++i; row += RSTR; j = i + 1; }
            v.w = row[j];
            *(float4*)(outp + p) = v;
        }
    }
    __syncwarp();                            // stage reusable for next strip
}

__global__ __launch_bounds__(64, 10)
void gram_hmma8(const float* __restrict__ in, float* __restrict__ out)
{
    __shared__ __align__(16) float stg[2][STGF];   // 8704 B

    const int tid  = threadIdx.x;
    const int w    = tid >> 5;               // warp = sample
    const int lane = tid & 31;

    float* outp = out + ((size_t)blockIdx.x * 2 + w) * NPAIR;

    // ---- Phase 1: build fragments directly from gmem (no smem, no ldmatrix).
    // Bh[t][j] lane l = bf16x2 of (f = 8t + (l>>2), d = 8j + 2*(l&3), d+1).
    uint32_t Bh[8][4], Bl[8][4];
    {
        const float2* src = (const float2*)(in + ((size_t)blockIdx.x * 2 + w) * 2048);
        const int rbase = lane >> 2;
        const int koff  = lane & 3;
        #pragma unroll
        for (int t = 0; t < 8; ++t) {
            const int f = 8 * t + rbase;
            #pragma unroll
            for (int j = 0; j < 4; ++j) {
                float2 v = src[f * 16 + 4 * j + koff];
                uint32_t hi, lo;
                asm("cvt.rn.bf16x2.f32 %0, %1, %2;" : "=r"(hi) : "f"(v.y), "f"(v.x));
                float q0 = v.x - __uint_as_float(hi << 16);
                float q1 = v.y - __uint_as_float(hi & 0xFFFF0000u);
                asm("cvt.rn.bf16x2.f32 %0, %1, %2;" : "=r"(lo) : "f"(q1), "f"(q0));
                Bh[t][j] = hi;
                Bl[t][j] = lo;
            }
        }
    }

    // ---- Phase 2: four row strips, A = reused B registers
    float* st = stg[w];
    strip<0>(Bh, Bl, st, outp, lane);
    strip<1>(Bh, Bl, st, outp, lane);
    strip<2>(Bh, Bl, st, outp, lane);
    strip<3>(Bh, Bl, st, outp, lane);
}

extern "C" void kernel_launch(void* const* d_in, const int* in_sizes, int n_in,
                              void* d_out, int out_size)
{
    const float* in  = (const float*)d_in[0];
    float*       out = (float*)d_out;
    int nb = in_sizes[0] / (NF * 32);      // 16384
    gram_hmma8<<<nb / 2, 64>>>(in, out);
}

// round 16
// speedup vs baseline: 1.1598x; 1.1598x over previous
#include <cuda_runtime.h>
#include <stdint.h>

#define NF 64
#define NPAIR 2016
#define RSTR 72                      // stage row stride (floats); 72 = 8 mod 32
#define STGF 1168                    // per-warp stage floats (15*72+3+64, rounded)

__device__ __forceinline__ void mma4(float* c,
                                     uint32_t a0, uint32_t a1, uint32_t a2, uint32_t a3,
                                     uint32_t b0, uint32_t b1) {
    asm volatile(
        "mma.sync.aligned.m16n8k16.row.col.f32.bf16.bf16.f32 "
        "{%0,%1,%2,%3}, {%4,%5,%6,%7}, {%8,%9}, {%0,%1,%2,%3};"
        : "+f"(c[0]), "+f"(c[1]), "+f"(c[2]), "+f"(c[3])
        : "r"(a0), "r"(a1), "r"(a2), "r"(a3), "r"(b0), "r"(b1));
}

// Strip R: gram rows [16R,16R+16). A fragments are reused B-tile registers.
// Stage layout: G[i][j] at  st[ir*RSTR + (ir>>2) + j]  (ir = strip-local row).
// Bank-proof: 72 ≡ 8 (mod 32) spreads 8 rows over bank-quads, and the
// (ir>>2) shift puts the wrapped half on odd banks -> all 32 STS lanes
// hit distinct banks. Stores are UNGUARDED (below-diagonal slots never read).
template<int R>
__device__ __forceinline__ void strip(const uint32_t Bh[8][4],
                                      const uint32_t Bl[8][4],
                                      float* st, float* outp, int lane)
{
    const int r0l = lane >> 2;               // strip-local rows r0l, r0l+8
    float* s0 = st + r0l * RSTR + (r0l >> 2) + 2 * (lane & 3);
    float* s1 = st + (r0l + 8) * RSTR + ((r0l + 8) >> 2) + 2 * (lane & 3);

    #pragma unroll
    for (int t = 2 * R; t < 8; ++t) {
        float c[4] = {0.f, 0.f, 0.f, 0.f};
        // hi.hi
        mma4(c, Bh[2*R][0], Bh[2*R+1][0], Bh[2*R][1], Bh[2*R+1][1], Bh[t][0], Bh[t][1]);
        mma4(c, Bh[2*R][2], Bh[2*R+1][2], Bh[2*R][3], Bh[2*R+1][3], Bh[t][2], Bh[t][3]);
        // hi.lo
        mma4(c, Bh[2*R][0], Bh[2*R+1][0], Bh[2*R][1], Bh[2*R+1][1], Bl[t][0], Bl[t][1]);
        mma4(c, Bh[2*R][2], Bh[2*R+1][2], Bh[2*R][3], Bh[2*R+1][3], Bl[t][2], Bl[t][3]);
        // lo.hi
        mma4(c, Bl[2*R][0], Bl[2*R+1][0], Bl[2*R][1], Bl[2*R+1][1], Bh[t][0], Bh[t][1]);
        mma4(c, Bl[2*R][2], Bl[2*R+1][2], Bl[2*R][3], Bl[2*R+1][3], Bh[t][2], Bh[t][3]);

        // unguarded, conflict-free scatter (4 x STS.32)
        s0[8 * t]     = c[0];
        s0[8 * t + 1] = c[1];
        s1[8 * t]     = c[2];
        s1[8 * t + 1] = c[3];
    }
    __syncwarp();

    // static per-row packed copy-out: all indices compile-time
    #pragma unroll
    for (int ir = 0; ir < 16; ++ir) {
        const int i   = 16 * R + ir;         // gram row (folds per unroll)
        const int len = 63 - i;              // valid elements in row i
        if (len > 0) {
            const float* src = st + ir * RSTR + (ir >> 2) + i + 1;
            float*       dst = outp + (i * (127 - i)) / 2;
            if (len >= 32) {
                dst[lane] = src[lane];                       // unpredicated
                if (lane + 32 < len) dst[lane + 32] = src[lane + 32];
            } else {
                if (lane < len) dst[lane] = src[lane];
            }
        }
    }
    __syncwarp();                            // stage reusable for next strip
}

__global__ __launch_bounds__(64, 10)
void gram_hmma9(const float* __restrict__ in, float* __restrict__ out)
{
    __shared__ __align__(16) float stg[2][STGF];   // 9344 B

    const int tid  = threadIdx.x;
    const int w    = tid >> 5;               // warp = sample
    const int lane = tid & 31;

    float* outp = out + ((size_t)blockIdx.x * 2 + w) * NPAIR;

    // ---- Phase 1: build fragments directly from gmem (no smem, no ldmatrix).
    // Bh[t][j] lane l = bf16x2 of (f = 8t + (l>>2), d = 8j + 2*(l&3), d+1).
    uint32_t Bh[8][4], Bl[8][4];
    {
        const float2* src = (const float2*)(in + ((size_t)blockIdx.x * 2 + w) * 2048);
        const int rbase = lane >> 2;
        const int koff  = lane & 3;
        #pragma unroll
        for (int t = 0; t < 8; ++t) {
            const int f = 8 * t + rbase;
            #pragma unroll
            for (int j = 0; j < 4; ++j) {
                float2 v = src[f * 16 + 4 * j + koff];
                uint32_t hi, lo;
                asm("cvt.rn.bf16x2.f32 %0, %1, %2;" : "=r"(hi) : "f"(v.y), "f"(v.x));
                float q0 = v.x - __uint_as_float(hi << 16);
                float q1 = v.y - __uint_as_float(hi & 0xFFFF0000u);
                asm("cvt.rn.bf16x2.f32 %0, %1, %2;" : "=r"(lo) : "f"(q1), "f"(q0));
                Bh[t][j] = hi;
                Bl[t][j] = lo;
            }
        }
    }

    // ---- Phase 2: four row strips, A = reused B registers
    float* st = stg[w];
    strip<0>(Bh, Bl, st, outp, lane);
    strip<1>(Bh, Bl, st, outp, lane);
    strip<2>(Bh, Bl, st, outp, lane);
    strip<3>(Bh, Bl, st, outp, lane);
}

extern "C" void kernel_launch(void* const* d_in, const int* in_sizes, int n_in,
                              void* d_out, int out_size)
{
    const float* in  = (const float*)d_in[0];
    float*       out = (float*)d_out;
    int nb = in_sizes[0] / (NF * 32);      // 16384
    gram_hmma9<<<nb / 2, 64>>>(in, out);
}

// round 17
// speedup vs baseline: 1.2605x; 1.0868x over previous
#include <cuda_runtime.h>
#include <stdint.h>

#define NF 64
#define NPAIR 2016
#define STGW 896                     // per-warp stage floats (max strip = 888)

__device__ __forceinline__ void mma4(float* c,
                                     uint32_t a0, uint32_t a1, uint32_t a2, uint32_t a3,
                                     uint32_t b0, uint32_t b1) {
    asm volatile(
        "mma.sync.aligned.m16n8k16.row.col.f32.f16.f16.f32 "
        "{%0,%1,%2,%3}, {%4,%5,%6,%7}, {%8,%9}, {%0,%1,%2,%3};"
        : "+f"(c[0]), "+f"(c[1]), "+f"(c[2]), "+f"(c[3])
        : "r"(a0), "r"(a1), "r"(a2), "r"(a3), "r"(b0), "r"(b1));
}

// Strip R: rows [16R,16R+16). A fragments are reused hi B-tile registers.
// 2-pass fp16 split: G ~= hi.hi + hi.lo  (|lo|<=2^-12|x| -> rel err ~2e-4).
// Packed region [S0,S0+SZ) staged then copied out as dense float4 (proven).
template<int R>
__device__ __forceinline__ void strip(const uint32_t Bh[8][4],
                                      const uint32_t Bl[8][4],
                                      float* st, float* outp, int lane)
{
    constexpr int S0 = (16 * R * (127 - 16 * R)) / 2;   // 0, 888, 1520, 1896
    constexpr int SZ = 888 - 256 * R;                   // 888, 632, 376, 120

    const int r0 = 16 * R + (lane >> 2);
    const int r1 = r0 + 8;
    const int b0 = ((r0 * (127 - r0)) >> 1) - r0 - 1 - S0;   // strip-relative
    const int b1 = ((r1 * (127 - r1)) >> 1) - r1 - 1 - S0;

    #pragma unroll
    for (int t = 2 * R; t < 8; ++t) {
        float c[4] = {0.f, 0.f, 0.f, 0.f};
        // hi.hi
        mma4(c, Bh[2*R][0], Bh[2*R+1][0], Bh[2*R][1], Bh[2*R+1][1], Bh[t][0], Bh[t][1]);
        mma4(c, Bh[2*R][2], Bh[2*R+1][2], Bh[2*R][3], Bh[2*R+1][3], Bh[t][2], Bh[t][3]);
        // hi.lo
        mma4(c, Bh[2*R][0], Bh[2*R+1][0], Bh[2*R][1], Bh[2*R+1][1], Bl[t][0], Bl[t][1]);
        mma4(c, Bh[2*R][2], Bh[2*R+1][2], Bh[2*R][3], Bh[2*R+1][3], Bl[t][2], Bl[t][3]);

        const int c0 = 8 * t + 2 * (lane & 3);
        if (t == 2 * R) {                    // diagonal tile: half 0 guarded
            if (c0     > r0) st[b0 + c0]     = c[0];
            if (c0 + 1 > r0) st[b0 + c0 + 1] = c[1];
        } else if (t == 2 * R + 1) {         // half 0 above diag, half 1 guarded
            st[b0 + c0]     = c[0];
            st[b0 + c0 + 1] = c[1];
            if (c0     > r1) st[b1 + c0]     = c[2];
            if (c0 + 1 > r1) st[b1 + c0 + 1] = c[3];
        } else {                             // fully above diagonal
            st[b0 + c0]     = c[0];
            st[b0 + c0 + 1] = c[1];
            st[b1 + c0]     = c[2];
            st[b1 + c0 + 1] = c[3];
        }
    }
    __syncwarp();

    // dense coalesced float4 copy-out of this strip's packed region
    constexpr int QUADS = SZ / 4;            // 222, 158, 94, 30
    #pragma unroll
    for (int qb = 0; qb < (QUADS + 31) / 32; ++qb) {
        int q = lane + qb * 32;
        if (QUADS % 32 == 0 || q < QUADS) {
            float4 v = *(const float4*)(st + q * 4);
            *(float4*)(outp + S0 + q * 4) = v;
        }
    }
    __syncwarp();                            // stage reusable for next strip
}

__global__ __launch_bounds__(64, 12)
void gram_hmma10(const float* __restrict__ in, float* __restrict__ out)
{
    __shared__ __align__(16) float stg[2][STGW];   // 7168 B

    const int tid  = threadIdx.x;
    const int w    = tid >> 5;               // warp = sample
    const int lane = tid & 31;

    float* outp = out + ((size_t)blockIdx.x * 2 + w) * NPAIR;

    // ---- Phase 1: build fp16 hi/lo fragments directly from gmem.
    // Bh[t][j] lane l = f16x2 of (f = 8t + (l>>2), d = 8j + 2*(l&3), d+1).
    uint32_t Bh[8][4], Bl[8][4];
    {
        const float2* src = (const float2*)(in + ((size_t)blockIdx.x * 2 + w) * 2048);
        const int rbase = lane >> 2;
        const int koff  = lane & 3;
        #pragma unroll
        for (int t = 0; t < 8; ++t) {
            const int f = 8 * t + rbase;
            #pragma unroll
            for (int j = 0; j < 4; ++j) {
                float2 v = src[f * 16 + 4 * j + koff];
                uint32_t hi, lo;
                asm("cvt.rn.f16x2.f32 %0, %1, %2;" : "=r"(hi) : "f"(v.y), "f"(v.x));
                float xr, yr;
                asm("{\n\t.reg .f16 l, h;\n\t"
                    "mov.b32 {l, h}, %2;\n\t"
                    "cvt.f32.f16 %0, l;\n\t"
                    "cvt.f32.f16 %1, h;\n\t}"
                    : "=f"(xr), "=f"(yr) : "r"(hi));
                asm("cvt.rn.f16x2.f32 %0, %1, %2;"
                    : "=r"(lo) : "f"(v.y - yr), "f"(v.x - xr));
                Bh[t][j] = hi;
                Bl[t][j] = lo;
            }
        }
    }

    // ---- Phase 2: four row strips, A = reused hi registers
    float* st = stg[w];
    strip<0>(Bh, Bl, st, outp, lane);
    strip<1>(Bh, Bl, st, outp, lane);
    strip<2>(Bh, Bl, st, outp, lane);
    strip<3>(Bh, Bl, st, outp, lane);
}

extern "C" void kernel_launch(void* const* d_in, const int* in_sizes, int n_in,
                              void* d_out, int out_size)
{
    const float* in  = (const float*)d_in[0];
    float*       out = (float*)d_out;
    int nb = in_sizes[0] / (NF * 32);      // 16384
    gram_hmma10<<<nb / 2, 64>>>(in, out);
}